// round 4
// baseline (speedup 1.0000x reference)
#include <cuda_runtime.h>

// SegmenterTensorFlow: windowed framing + overlap-add reconstruction.
// B=8, N=4194304, seg=1024, hop=512 -> NSEG=8191, out_len=N.
//
// d_out layout: X [B, NSEG, SEG] followed by x_rec [B, N].
//
// hop = seg/2 => sample n (s0 = n>>9, m = n&511) contributes to:
//   X[b, s0,   m    ]  (valid while s0 <  NSEG)
//   X[b, s0-1, m+512]  (valid while s0 >= 1)
// x_rec[b,n] = x[b,n] * (v0*aw[m]*sw[m] + v1*aw[m+512]*sw[m+512]).
//
// R4: phase-resident threads. Thread owns fixed m = tid*4, loops over
// segments; window values live in registers across the loop, so the body
// is the minimal stream: 1 LDG.128 + 3 STG.128 + pointer adds.
// (R1/R3 spent half their L1tex wavefronts reloading windows every element.)

#define BB    8
#define NN    4194304
#define SEG   1024
#define HOP   512
#define NSEG  8191
#define NSVAL 8192      // s0 takes values 0..8191
#define CHUNK 4         // segments per block

__device__ __forceinline__ float4 mul4(float4 a, float4 b) {
    float4 r; r.x = a.x*b.x; r.y = a.y*b.y; r.z = a.z*b.z; r.w = a.w*b.w;
    return r;
}

__global__ __launch_bounds__(128)
void seg_phase_kernel(const float* __restrict__ x,
                      const float* __restrict__ aw,
                      const float* __restrict__ sw,
                      float* __restrict__ Xout,
                      float* __restrict__ rec)
{
    const int tid  = threadIdx.x;          // 0..127
    const int b    = blockIdx.y;           // 0..7
    const int s_lo = blockIdx.x * CHUNK;   // 0..8188
    const int m    = tid << 2;             // float4 phase slot, 0..508

    // Windows: loaded once, register-resident for the whole loop.
    float4 awl = *reinterpret_cast<const float4*>(aw + m);
    float4 awh = *reinterpret_cast<const float4*>(aw + m + HOP);
    float4 swl = *reinterpret_cast<const float4*>(sw + m);
    float4 swh = *reinterpret_cast<const float4*>(sw + m + HOP);
    float4 cwl = mul4(awl, swl);           // rec weight, lo half
    float4 cwh = mul4(awh, swh);           // rec weight, hi half

    const size_t nbase = ((size_t)b << 22) + (size_t)s_lo * HOP + m;
    const float* xp   = x   + nbase;
    float*       recp = rec + nbase;
    float*       X0   = Xout + ((size_t)b * NSEG + s_lo) * SEG + m; // [b,s,m]
    float*       X1   = X0 - HOP;                                   // [b,s-1,m+512]

    #pragma unroll
    for (int k = 0; k < CHUNK; ++k) {
        const int  s  = s_lo + k;
        const bool v0 = (s < NSEG);
        const bool v1 = (s >= 1);

        float4 xv = __ldcs(reinterpret_cast<const float4*>(xp));

        if (v0) __stcs(reinterpret_cast<float4*>(X0), mul4(xv, awl));
        if (v1) __stcs(reinterpret_cast<float4*>(X1), mul4(xv, awh));

        const float w0 = v0 ? 1.0f : 0.0f;
        const float w1 = v1 ? 1.0f : 0.0f;
        float4 r;
        r.x = xv.x * (w0 * cwl.x + w1 * cwh.x);
        r.y = xv.y * (w0 * cwl.y + w1 * cwh.y);
        r.z = xv.z * (w0 * cwl.z + w1 * cwh.z);
        r.w = xv.w * (w0 * cwl.w + w1 * cwh.w);
        __stcs(reinterpret_cast<float4*>(recp), r);

        xp   += HOP;
        recp += HOP;
        X0   += SEG;
        X1   += SEG;
    }
}

extern "C" void kernel_launch(void* const* d_in, const int* in_sizes, int n_in,
                              void* d_out, int out_size)
{
    const float* x  = (const float*)d_in[0];
    const float* aw = (const float*)d_in[1];
    const float* sw = (const float*)d_in[2];

    float* Xout = (float*)d_out;
    float* rec  = Xout + (size_t)BB * NSEG * SEG;

    dim3 grid(NSVAL / CHUNK, BB);          // 2048 x 8 = 16384 blocks
    seg_phase_kernel<<<grid, 128>>>(x, aw, sw, Xout, rec);
}

// round 6
// speedup vs baseline: 1.0011x; 1.0011x over previous
#include <cuda_runtime.h>

// SegmenterTensorFlow: windowed framing + overlap-add reconstruction.
// B=8, N=4194304, seg=1024, hop=512 -> NSEG=8191, out_len=N.
//
// d_out layout: X [B, NSEG, SEG] followed by x_rec [B, N].
//
// hop = seg/2 => sample n (s0 = n>>9, m = n&511) contributes to:
//   X[b, s0,   m    ]  (valid while s0 <  NSEG)
//   X[b, s0-1, m+512]  (valid while s0 >= 1)
// x_rec[b,n] = x[b,n] * (v0*aw[m]*sw[m] + v1*aw[m+512]*sw[m+512]).
//
// R6: R5 retry with legal PTX encoding. sm_103 ptxas rejects the inline
// .L2::evict_last qualifier on v4.f32; the createpolicy + .L2::cache_hint
// form carries the same evict-last policy at any width.
//   x loads  : ld.global.nc.L2::cache_hint.v4.f32 (policy = evict_last)
//   stores   : .cs evict-first (write-once streams must not displace x)

#define BB    8
#define NN    4194304
#define SEG   1024
#define HOP   512
#define NSEG  8191
#define NSVAL 8192      // s0 takes values 0..8191
#define CHUNK 4         // segments per block

__device__ __forceinline__ float4 mul4(float4 a, float4 b) {
    float4 r; r.x = a.x*b.x; r.y = a.y*b.y; r.z = a.z*b.z; r.w = a.w*b.w;
    return r;
}

// v4.f32 non-coherent load with L2 evict-last cache policy
__device__ __forceinline__ float4 ldg_evict_last4(const float* p, unsigned long long pol) {
    float4 v;
    asm volatile("ld.global.nc.L2::cache_hint.v4.f32 {%0,%1,%2,%3}, [%4], %5;"
                 : "=f"(v.x), "=f"(v.y), "=f"(v.z), "=f"(v.w)
                 : "l"(p), "l"(pol));
    return v;
}

__global__ __launch_bounds__(128)
void seg_phase_kernel(const float* __restrict__ x,
                      const float* __restrict__ aw,
                      const float* __restrict__ sw,
                      float* __restrict__ Xout,
                      float* __restrict__ rec)
{
    const int tid  = threadIdx.x;          // 0..127
    const int b    = blockIdx.y;           // 0..7
    const int s_lo = blockIdx.x * CHUNK;   // 0..8188
    const int m    = tid << 2;             // float4 phase slot, 0..508

    // L2 evict-last policy for the x stream (re-read every graph replay)
    unsigned long long pol;
    asm volatile("createpolicy.fractional.L2::evict_last.b64 %0, 1.0;" : "=l"(pol));

    // Windows: loaded once, register-resident for the whole loop.
    float4 awl = *reinterpret_cast<const float4*>(aw + m);
    float4 awh = *reinterpret_cast<const float4*>(aw + m + HOP);
    float4 swl = *reinterpret_cast<const float4*>(sw + m);
    float4 swh = *reinterpret_cast<const float4*>(sw + m + HOP);
    float4 cwl = mul4(awl, swl);           // rec weight, lo half
    float4 cwh = mul4(awh, swh);           // rec weight, hi half

    const size_t nbase = ((size_t)b << 22) + (size_t)s_lo * HOP + m;
    const float* xp   = x   + nbase;
    float*       recp = rec + nbase;
    float*       X0   = Xout + ((size_t)b * NSEG + s_lo) * SEG + m; // [b,s,m]
    float*       X1   = X0 - HOP;                                   // [b,s-1,m+512]

    #pragma unroll
    for (int k = 0; k < CHUNK; ++k) {
        const int  s  = s_lo + k;
        const bool v0 = (s < NSEG);
        const bool v1 = (s >= 1);

        float4 xv = ldg_evict_last4(xp, pol);

        if (v0) __stcs(reinterpret_cast<float4*>(X0), mul4(xv, awl));
        if (v1) __stcs(reinterpret_cast<float4*>(X1), mul4(xv, awh));

        const float w0 = v0 ? 1.0f : 0.0f;
        const float w1 = v1 ? 1.0f : 0.0f;
        float4 r;
        r.x = xv.x * (w0 * cwl.x + w1 * cwh.x);
        r.y = xv.y * (w0 * cwl.y + w1 * cwh.y);
        r.z = xv.z * (w0 * cwl.z + w1 * cwh.z);
        r.w = xv.w * (w0 * cwl.w + w1 * cwh.w);
        __stcs(reinterpret_cast<float4*>(recp), r);

        xp   += HOP;
        recp += HOP;
        X0   += SEG;
        X1   += SEG;
    }
}

extern "C" void kernel_launch(void* const* d_in, const int* in_sizes, int n_in,
                              void* d_out, int out_size)
{
    const float* x  = (const float*)d_in[0];
    const float* aw = (const float*)d_in[1];
    const float* sw = (const float*)d_in[2];

    float* Xout = (float*)d_out;
    float* rec  = Xout + (size_t)BB * NSEG * SEG;

    dim3 grid(NSVAL / CHUNK, BB);          // 2048 x 8 = 16384 blocks
    seg_phase_kernel<<<grid, 128>>>(x, aw, sw, Xout, rec);
}